// round 2
// baseline (speedup 1.0000x reference)
#include <cuda_runtime.h>
#include <math.h>

// ArcFace loss, single-pass streaming formulation.
//   loss_row = log( sum_c exp(S*clamp(pred)) - exp(S*tgt_cos) + exp(S*tgt_m) ) - S*tgt_m
//   out = mean(loss_row)
// No max-subtraction needed: S*clamp(x) in [-30,30] -> exp in [1e-13,1e13],
// row sum <= 3.2e17, safely inside fp32 range.

#define S_SCALE   30.0f
// cos(0.5), sin(0.5)
#define COS_M     0.8775825618903728f
#define SIN_M     0.479425538604203f
// sin(pi-M)*M = sin(M)*M
#define MM_CONST  (0.479425538604203f * 0.5f)
// cos(pi-M) = -cos(M)
#define THRESH    (-0.8775825618903728f)

#define MAX_ROWS 16384
__device__ float g_row_loss[MAX_ROWS];
__device__ int   g_tgt_is64;   // 1 if target buffer is int64, 0 if int32

__device__ __forceinline__ float clamp1(float x) {
    return fminf(1.0f, fmaxf(-1.0f, x));
}

// Decide whether the target buffer holds int64 or int32 values.
// Interpreted as int32 words:
//   - int64 layout: words at odd indices < n are the HIGH words of the
//     first n/2 targets -> all zero (targets are small nonnegative ints).
//   - int32 layout: words at odd indices are actual random targets ->
//     OR is nonzero with probability 1 - (1/C)^(n/2) ~= 1.
// Only touches word indices < n, in-bounds for both layouts. Deterministic.
__global__ void __launch_bounds__(256)
detect_tgt_dtype_kernel(const int* __restrict__ tgt_words, int n)
{
    __shared__ int warp_or[8];
    int acc = 0;
    for (int i = 1 + 2 * threadIdx.x; i < n; i += 2 * blockDim.x)
        acc |= tgt_words[i];
    #pragma unroll
    for (int off = 16; off > 0; off >>= 1)
        acc |= __shfl_xor_sync(0xFFFFFFFFu, acc, off);
    int lane = threadIdx.x & 31, wid = threadIdx.x >> 5;
    if (lane == 0) warp_or[wid] = acc;
    __syncthreads();
    if (threadIdx.x == 0) {
        int r = 0;
        #pragma unroll
        for (int w = 0; w < 8; w++) r |= warp_or[w];
        g_tgt_is64 = (r == 0) ? 1 : 0;
    }
}

__device__ __forceinline__ float block_reduce_sum(float v) {
    __shared__ float warp_sums[32];
    int lane = threadIdx.x & 31;
    int wid  = threadIdx.x >> 5;
    #pragma unroll
    for (int off = 16; off > 0; off >>= 1)
        v += __shfl_xor_sync(0xFFFFFFFFu, v, off);
    if (lane == 0) warp_sums[wid] = v;
    __syncthreads();
    int nwarps = (blockDim.x + 31) >> 5;
    if (wid == 0) {
        v = (lane < nwarps) ? warp_sums[lane] : 0.0f;
        #pragma unroll
        for (int off = 16; off > 0; off >>= 1)
            v += __shfl_xor_sync(0xFFFFFFFFu, v, off);
    }
    return v;  // valid in warp 0
}

__global__ void __launch_bounds__(256)
arcface_row_kernel(const float* __restrict__ pred,
                   const void* __restrict__ target,
                   int C)
{
    const int row = blockIdx.x;
    const float* rowp = pred + (size_t)row * (size_t)C;
    const float4* p4 = reinterpret_cast<const float4*>(rowp);
    const int nvec = C >> 2;          // C divisible by 4 (32000)

    float acc = 0.0f;
    // Strided float4 stream; each lane accumulates exp(S*clamp(x)).
    #pragma unroll 4
    for (int i = threadIdx.x; i < nvec; i += blockDim.x) {
        float4 v = p4[i];
        acc += __expf(S_SCALE * clamp1(v.x));
        acc += __expf(S_SCALE * clamp1(v.y));
        acc += __expf(S_SCALE * clamp1(v.z));
        acc += __expf(S_SCALE * clamp1(v.w));
    }
    // Tail (not hit for C=32000, kept for generality)
    for (int i = (nvec << 2) + threadIdx.x; i < C; i += blockDim.x)
        acc += __expf(S_SCALE * clamp1(rowp[i]));

    float total = block_reduce_sum(acc);

    if (threadIdx.x == 0) {
        long long t;
        if (g_tgt_is64)
            t = ((const long long*)target)[row];
        else
            t = (long long)((const int*)target)[row];
        float tc = clamp1(rowp[t]);
        // cos(acos(tc)+M) = tc*cosM - sqrt(1-tc^2)*sinM
        float tm_hard = tc * COS_M - sqrtf(fmaxf(0.0f, 1.0f - tc * tc)) * SIN_M;
        float tm = (tc > THRESH) ? tm_hard : (tc - MM_CONST);
        float sum = total - __expf(S_SCALE * tc) + __expf(S_SCALE * tm);
        g_row_loss[row] = logf(sum) - S_SCALE * tm;
    }
}

__global__ void __launch_bounds__(1024)
arcface_reduce_kernel(float* __restrict__ out, int n)
{
    __shared__ double warp_sums[32];
    double acc = 0.0;
    for (int i = threadIdx.x; i < n; i += blockDim.x)
        acc += (double)g_row_loss[i];
    int lane = threadIdx.x & 31;
    int wid  = threadIdx.x >> 5;
    #pragma unroll
    for (int off = 16; off > 0; off >>= 1)
        acc += __shfl_xor_sync(0xFFFFFFFFu, acc, off);
    if (lane == 0) warp_sums[wid] = acc;
    __syncthreads();
    if (wid == 0) {
        acc = (lane < (blockDim.x >> 5)) ? warp_sums[lane] : 0.0;
        #pragma unroll
        for (int off = 16; off > 0; off >>= 1)
            acc += __shfl_xor_sync(0xFFFFFFFFu, acc, off);
        if (lane == 0)
            out[0] = (float)(acc / (double)n);
    }
}

extern "C" void kernel_launch(void* const* d_in, const int* in_sizes, int n_in,
                              void* d_out, int out_size)
{
    const float* pred   = (const float*)d_in[0];
    const void*  target = d_in[1];
    float*       out    = (float*)d_out;

    const int n = in_sizes[1];              // number of rows (targets)
    const int C = in_sizes[0] / n;          // classes per row

    detect_tgt_dtype_kernel<<<1, 256>>>((const int*)target, n);
    arcface_row_kernel<<<n, 256>>>(pred, target, C);
    arcface_reduce_kernel<<<1, 1024>>>(out, n);
}